// round 16
// baseline (speedup 1.0000x reference)
#include <cuda_runtime.h>
#include <math.h>

#define NN 50000
#define EE 600000

// ---------------- scratch (device globals; allocation-free) ----------------
__device__ float g_q[NN*128];
__device__ float g_k[NN*128];
__device__ float g_v[NN*128];
__device__ float g_qt[NN*64];
__device__ float g_Wc[64*64];       // per-head We@Wp fold
__device__ int   g_deg[NN];
__device__ int   g_rowstart[NN+1];
__device__ int   g_cursor[NN];
__device__ int2  g_csr[EE];
__device__ int   g_scan_done;

// ---------------- K1: edge-count + LN1 + QKV GEMM + qt GEMM (64-node tiles) -
__global__ void __launch_bounds__(512) k_ln_qkv(
    const float* __restrict__ x,  const int* __restrict__ ei,
    const float* __restrict__ Wq, const float* __restrict__ bq,
    const float* __restrict__ Wk, const float* __restrict__ bk,
    const float* __restrict__ Wv, const float* __restrict__ bv,
    const float* __restrict__ We,
    const float* __restrict__ g1, const float* __restrict__ b1, int n, int e)
{
    extern __shared__ float sm[];
    float* Ws = sm;               // 64*384
    float* bs = Ws + 64*384;      // 384
    float* hs = bs + 384;         // 64*68
    float* qs = hs + 64*68;       // 64*132
    float* Wt = qs + 64*132;      // 128*36
    const int tid = threadIdx.x;

    for (int ed = blockIdx.x*blockDim.x + tid; ed < e; ed += gridDim.x*blockDim.x)
        atomicAdd(&g_deg[ei[e + ed]], 1);

    for (int i = tid; i < 64*128; i += 512) {
        int kk = i >> 7, c = i & 127;
        Ws[kk*384 + c]       = Wq[i];
        Ws[kk*384 + 128 + c] = Wk[i];
        Ws[kk*384 + 256 + c] = Wv[i];
    }
    if (tid < 384) bs[tid] = (tid < 128) ? bq[tid] : (tid < 256 ? bk[tid-128] : bv[tid-256]);
    for (int i = tid; i < 32*128; i += 512) {
        int d = i & 31, cg = i >> 5;
        Wt[cg*36 + d] = We[d*128 + cg];
    }
    __syncthreads();
    const int tx = tid & 31, ty = tid >> 5;
    const int node64 = tid >> 3, part = tid & 7;
    const int tx16 = tid & 15, ty16 = tid >> 4;
    const int hql = tx16 >> 3;
    const int dq  = (tx16 & 7) * 4;
    const int ntiles = (n + 63) >> 6;
    for (int tile = blockIdx.x; tile < ntiles; tile += gridDim.x) {
        const int n0 = tile << 6;
        {   // LayerNorm
            int gn = n0 + node64;
            float v0[8];
            if (gn < n) {
                float4 a  = *(const float4*)&x[gn*64 + part*8];
                float4 b4 = *(const float4*)&x[gn*64 + part*8 + 4];
                v0[0]=a.x; v0[1]=a.y; v0[2]=a.z; v0[3]=a.w;
                v0[4]=b4.x; v0[5]=b4.y; v0[6]=b4.z; v0[7]=b4.w;
            } else {
                #pragma unroll
                for (int i=0;i<8;i++) v0[i]=0.f;
            }
            float s=0.f, ss=0.f;
            #pragma unroll
            for (int i=0;i<8;i++){ s+=v0[i]; ss+=v0[i]*v0[i]; }
            #pragma unroll
            for (int m=1;m<8;m<<=1){
                s  += __shfl_xor_sync(0xffffffffu, s,  m);
                ss += __shfl_xor_sync(0xffffffffu, ss, m);
            }
            float mean = s*(1.f/64.f);
            float rstd = rsqrtf(ss*(1.f/64.f) - mean*mean + 1e-5f);
            int c = part*8;
            #pragma unroll
            for (int i=0;i<8;i++)
                hs[node64*68 + c + i] = (v0[i]-mean)*rstd*g1[c+i] + b1[c+i];
        }
        __syncthreads();
        {   // QKV GEMM
            float aq[4][4], ak[4][4], av[4][4];
            const float4 bqv = *(const float4*)&bs[tx*4];
            const float4 bkv = *(const float4*)&bs[128 + tx*4];
            const float4 bvv = *(const float4*)&bs[256 + tx*4];
            #pragma unroll
            for (int i=0;i<4;i++){
                aq[i][0]=bqv.x; aq[i][1]=bqv.y; aq[i][2]=bqv.z; aq[i][3]=bqv.w;
                ak[i][0]=bkv.x; ak[i][1]=bkv.y; ak[i][2]=bkv.z; ak[i][3]=bkv.w;
                av[i][0]=bvv.x; av[i][1]=bvv.y; av[i][2]=bvv.z; av[i][3]=bvv.w;
            }
            #pragma unroll 4
            for (int kk=0; kk<64; kk++) {
                const float4 wq = *(const float4*)&Ws[kk*384 + tx*4];
                const float4 wk = *(const float4*)&Ws[kk*384 + 128 + tx*4];
                const float4 wv = *(const float4*)&Ws[kk*384 + 256 + tx*4];
                #pragma unroll
                for (int i=0;i<4;i++){
                    const float h = hs[(ty*4+i)*68 + kk];
                    aq[i][0]+=h*wq.x; aq[i][1]+=h*wq.y; aq[i][2]+=h*wq.z; aq[i][3]+=h*wq.w;
                    ak[i][0]+=h*wk.x; ak[i][1]+=h*wk.y; ak[i][2]+=h*wk.z; ak[i][3]+=h*wk.w;
                    av[i][0]+=h*wv.x; av[i][1]+=h*wv.y; av[i][2]+=h*wv.z; av[i][3]+=h*wv.w;
                }
            }
            #pragma unroll
            for (int i=0;i<4;i++){
                const int r = ty*4 + i;
                const int gn = n0 + r;
                const float4 qv = make_float4(aq[i][0],aq[i][1],aq[i][2],aq[i][3]);
                *(float4*)&qs[r*132 + tx*4] = qv;
                if (gn < n) {
                    *(float4*)&g_q[gn*128 + tx*4] = qv;
                    *(float4*)&g_k[gn*128 + tx*4] = make_float4(ak[i][0],ak[i][1],ak[i][2],ak[i][3]);
                    *(float4*)&g_v[gn*128 + tx*4] = make_float4(av[i][0],av[i][1],av[i][2],av[i][3]);
                }
            }
        }
        __syncthreads();
        {   // qt GEMM
            float a2[2][4] = {{0.f,0.f,0.f,0.f},{0.f,0.f,0.f,0.f}};
            const int cbase = hql*64;
            #pragma unroll 4
            for (int c=0; c<64; c++) {
                const float4 w = *(const float4*)&Wt[(cbase + c)*36 + dq];
                const float q0 = qs[(ty16*2+0)*132 + cbase + c];
                const float q1 = qs[(ty16*2+1)*132 + cbase + c];
                a2[0][0]+=q0*w.x; a2[0][1]+=q0*w.y; a2[0][2]+=q0*w.z; a2[0][3]+=q0*w.w;
                a2[1][0]+=q1*w.x; a2[1][1]+=q1*w.y; a2[1][2]+=q1*w.z; a2[1][3]+=q1*w.w;
            }
            #pragma unroll
            for (int r=0;r<2;r++){
                const int gn = n0 + ty16*2 + r;
                if (gn < n)
                    *(float4*)&g_qt[gn*64 + tx16*4] =
                        make_float4(a2[r][0],a2[r][1],a2[r][2],a2[r][3]);
            }
        }
        __syncthreads();
    }
}

// ------- K2: coalesced scan (block 0) + Wc=We@Wp (block 1) + CSR fill -------
__global__ void __launch_bounds__(1024) k_scanfill(
    const int* __restrict__ ei, const float* __restrict__ We,
    const float* __restrict__ Wp, int e, int n)
{
    const int tid = threadIdx.x;
    if (blockIdx.x == 0) {
        __shared__ int buf[4096];
        __shared__ int wsum[32];
        __shared__ int carry_s;
        int carry = 0;
        const int lane = tid & 31, w = tid >> 5;
        for (int base = 0; base < n; base += 4096) {
            #pragma unroll
            for (int k = 0; k < 4; k++) {
                int idx = base + tid + k*1024;
                buf[tid + k*1024] = (idx < n) ? g_deg[idx] : 0;
            }
            __syncthreads();
            const int v0 = buf[tid*4], v1 = buf[tid*4+1], v2 = buf[tid*4+2], v3 = buf[tid*4+3];
            const int tsum = v0+v1+v2+v3;
            int sc = tsum;
            #pragma unroll
            for (int o=1;o<32;o<<=1){ int t2=__shfl_up_sync(0xffffffffu, sc, o); if(lane>=o) sc+=t2; }
            if (lane==31) wsum[w]=sc;
            __syncthreads();
            if (w==0){
                int s2 = wsum[lane];
                #pragma unroll
                for (int o=1;o<32;o<<=1){ int t2=__shfl_up_sync(0xffffffffu, s2, o); if(lane>=o) s2+=t2; }
                wsum[lane]=s2;
            }
            __syncthreads();
            const int excl = sc - tsum + (w>0 ? wsum[w-1] : 0) + carry;
            const int p0 = excl, p1 = p0+v0, p2 = p1+v1, p3 = p2+v2;
            const int gidx = base + tid*4;
            if (gidx + 3 < n) {
                g_rowstart[gidx]=p0; g_rowstart[gidx+1]=p1; g_rowstart[gidx+2]=p2; g_rowstart[gidx+3]=p3;
                g_cursor[gidx]=p0;   g_cursor[gidx+1]=p1;   g_cursor[gidx+2]=p2;   g_cursor[gidx+3]=p3;
            } else {
                const int pv[4] = {p0,p1,p2,p3};
                #pragma unroll
                for (int k2=0;k2<4;k2++)
                    if (gidx+k2 < n) { g_rowstart[gidx+k2]=pv[k2]; g_cursor[gidx+k2]=pv[k2]; }
            }
            if (tid==1023) carry_s = p3 + v3;
            __syncthreads();
            carry = carry_s;
        }
        if (tid==0) {
            g_rowstart[n] = carry;
            __threadfence();
            atomicExch(&g_scan_done, 1);
        }
    } else if (blockIdx.x == 1) {
        for (int i = tid; i < 4096; i += 1024) {
            const int kk = i >> 6;
            const int c  = i & 63;
            const int h  = kk >> 5, d = kk & 31;
            const float* wer = We + d*128 + h*64;
            const float* wpr = Wp + (h*64)*64 + c;
            float s = 0.f;
            #pragma unroll 8
            for (int t = 0; t < 64; t++) s += wer[t] * wpr[t*64];
            g_Wc[kk*64 + c] = s;
        }
        if (tid==0) { while (atomicAdd(&g_scan_done, 0) == 0) __nanosleep(128); }
    } else {
        if (tid==0) { while (atomicAdd(&g_scan_done, 0) == 0) __nanosleep(128); }
    }
    __syncthreads();
    const int gtid = blockIdx.x*blockDim.x + tid;
    const int stride = gridDim.x*blockDim.x;
    for (int ed = gtid; ed < e; ed += stride) {
        const int src = ei[ed];
        const int tgt = ei[e + ed];
        const int pos = atomicAdd(&g_cursor[tgt], 1);
        g_csr[pos] = make_int2(src, ed);
    }
    for (int i = gtid; i < n; i += stride) g_deg[i] = 0;
}

// ------ K3: FUSED aggregation + epilogue (64-node tiles, 2 CTA/SM) ----------
__global__ void __launch_bounds__(256) k_aggepi(
    float* __restrict__ out,
    const float* __restrict__ x,   const float* __restrict__ ea,
    const float* __restrict__ Wp,  const float* __restrict__ bp,
    const float* __restrict__ lg,  const float* __restrict__ lb,
    const float* __restrict__ W1,  const float* __restrict__ b1,
    const float* __restrict__ W2,  const float* __restrict__ b2, int n)
{
    extern __shared__ float sm[];
    float* Wps = sm;               // 8192
    float* W1s = Wps + 8192;       // 4096
    float* bps = W1s + 4096;       // 64
    float* b1s = bps + 64;
    float* b2s = b1s + 64;
    float* lgs = b2s + 64;
    float* lbs = lgs + 64;
    float* pool = lbs + 64;        // 13056 floats, aliased across stages
    float* avs = pool;             // [64][128] agg output
    float* tas = pool + 8192;      // [64][64]  agg output
    float* osh = pool;             // [64][68] after B
    float* hsh = pool + 4352;      // [64][68]
    float* msh = pool + 8704;      // [64][68]
    const int tid = threadIdx.x;
    if (blockIdx.x == 0 && tid == 0) atomicExch(&g_scan_done, 0);
    for (int i = tid; i < 8192; i += 256) Wps[i] = Wp[i];
    for (int i = tid; i < 4096; i += 256) W1s[i] = W1[i];
    if (tid < 64) { bps[tid]=bp[tid]; b1s[tid]=b1[tid]; b2s[tid]=b2[tid];
                    lgs[tid]=lg[tid]; lbs[tid]=lb[tid]; }
    __syncthreads();
    const int warp = tid >> 5, lane = tid & 31;
    const int h = lane >> 4, j = lane & 15;
    const int cg = tid & 15;
    const int rg = tid >> 4;
    const int nodeq = tid >> 2, partq = tid & 3;
    const float4* wc4 = (const float4*)g_Wc;
    const float4* w24 = (const float4*)W2;
    const int ntiles = (n + 63) >> 6;
    for (int tile = blockIdx.x; tile < ntiles; tile += gridDim.x) {
        const int n0 = tile << 6;
        const int nrem = n - n0;
        // ---- stage A (fused agg): warp-per-node ILP-2, results -> smem ----
        #pragma unroll 1
        for (int i = 0; i < 8; i++) {
            const int ni = warp*8 + i;
            const int node = n0 + ni;
            if (node >= n) break;
            const int r0 = g_rowstart[node], r1 = g_rowstart[node + 1];
            const float4 q4  = *(const float4*)&g_q[node*128 + lane*4];
            const float2 qt2 = *(const float2*)&g_qt[node*64 + h*32 + j*2];
            float den = 0.f;
            float4 acc = make_float4(0.f, 0.f, 0.f, 0.f);
            float2 tac = make_float2(0.f, 0.f);
            int p = r0;
            for (; p + 1 < r1; p += 2) {
                const int2 se0 = g_csr[p];
                const int2 se1 = g_csr[p+1];
                const float4 k0 = *(const float4*)&g_k[se0.x*128 + lane*4];
                const float4 k1 = *(const float4*)&g_k[se1.x*128 + lane*4];
                const float4 v0 = *(const float4*)&g_v[se0.x*128 + lane*4];
                const float4 v1 = *(const float4*)&g_v[se1.x*128 + lane*4];
                const float2 e0 = *(const float2*)&ea[se0.y*32 + j*2];
                const float2 e1 = *(const float2*)&ea[se1.y*32 + j*2];
                float s0 = q4.x*k0.x + q4.y*k0.y + q4.z*k0.z + q4.w*k0.w
                         + qt2.x*e0.x + qt2.y*e0.y;
                float s1 = q4.x*k1.x + q4.y*k1.y + q4.z*k1.z + q4.w*k1.w
                         + qt2.x*e1.x + qt2.y*e1.y;
                #pragma unroll
                for (int mm = 1; mm < 16; mm <<= 1) {
                    s0 += __shfl_xor_sync(0xffffffffu, s0, mm);
                    s1 += __shfl_xor_sync(0xffffffffu, s1, mm);
                }
                const float ex0 = __expf(s0 * 0.125f);
                const float ex1 = __expf(s1 * 0.125f);
                den += ex0 + ex1;
                acc.x += ex0*v0.x + ex1*v1.x;
                acc.y += ex0*v0.y + ex1*v1.y;
                acc.z += ex0*v0.z + ex1*v1.z;
                acc.w += ex0*v0.w + ex1*v1.w;
                tac.x += ex0*e0.x + ex1*e1.x;
                tac.y += ex0*e0.y + ex1*e1.y;
            }
            if (p < r1) {
                const int2 se = g_csr[p];
                const float4 k4 = *(const float4*)&g_k[se.x*128 + lane*4];
                const float4 v4 = *(const float4*)&g_v[se.x*128 + lane*4];
                const float2 e2 = *(const float2*)&ea[se.y*32 + j*2];
                float s = q4.x*k4.x + q4.y*k4.y + q4.z*k4.z + q4.w*k4.w
                        + qt2.x*e2.x + qt2.y*e2.y;
                #pragma unroll
                for (int mm = 1; mm < 16; mm <<= 1) s += __shfl_xor_sync(0xffffffffu, s, mm);
                const float ex = __expf(s * 0.125f);
                den += ex;
                acc.x += ex*v4.x; acc.y += ex*v4.y; acc.z += ex*v4.z; acc.w += ex*v4.w;
                tac.x += ex*e2.x; tac.y += ex*e2.y;
            }
            const float inv = 1.f / (den + 1e-8f);
            acc.x *= inv; acc.y *= inv; acc.z *= inv; acc.w *= inv;
            tac.x *= inv; tac.y *= inv;
            *(float4*)&avs[ni*128 + lane*4]    = acc;
            *(float2*)&tas[ni*64 + h*32 + j*2] = tac;
        }
        __syncthreads();
        // ---- stage B: acc = aggv@Wp + tacc@Wc + bp ----
        float acc[4][4];
        {
            const float4 bpv = *(const float4*)&bps[cg*4];
            #pragma unroll
            for (int r=0;r<4;r++){ acc[r][0]=bpv.x; acc[r][1]=bpv.y; acc[r][2]=bpv.z; acc[r][3]=bpv.w; }
            #pragma unroll 2
            for (int kk = 0; kk < 128; kk += 4) {
                float4 a[4], w[4];
                #pragma unroll
                for (int r=0;r<4;r++) a[r] = *(const float4*)&avs[(rg*4+r)*128 + kk];
                #pragma unroll
                for (int i=0;i<4;i++) w[i] = *(const float4*)&Wps[(kk+i)*64 + cg*4];
                #pragma unroll
                for (int r=0;r<4;r++){
                    acc[r][0]+=a[r].x*w[0].x + a[r].y*w[1].x + a[r].z*w[2].x + a[r].w*w[3].x;
                    acc[r][1]+=a[r].x*w[0].y + a[r].y*w[1].y + a[r].z*w[2].y + a[r].w*w[3].y;
                    acc[r][2]+=a[r].x*w[0].z + a[r].y*w[1].z + a[r].z*w[2].z + a[r].w*w[3].z;
                    acc[r][3]+=a[r].x*w[0].w + a[r].y*w[1].w + a[r].z*w[2].w + a[r].w*w[3].w;
                }
            }
            #pragma unroll 2
            for (int kk = 0; kk < 64; kk += 4) {
                float4 t[4], w[4];
                #pragma unroll
                for (int r=0;r<4;r++) t[r] = *(const float4*)&tas[(rg*4+r)*64 + kk];
                #pragma unroll
                for (int i=0;i<4;i++) w[i] = __ldg(&wc4[(kk+i)*16 + cg]);
                #pragma unroll
                for (int r=0;r<4;r++){
                    acc[r][0]+=t[r].x*w[0].x + t[r].y*w[1].x + t[r].z*w[2].x + t[r].w*w[3].x;
                    acc[r][1]+=t[r].x*w[0].y + t[r].y*w[1].y + t[r].z*w[2].y + t[r].w*w[3].y;
                    acc[r][2]+=t[r].x*w[0].z + t[r].y*w[1].z + t[r].z*w[2].z + t[r].w*w[3].z;
                    acc[r][3]+=t[r].x*w[0].w + t[r].y*w[1].w + t[r].z*w[2].w + t[r].w*w[3].w;
                }
            }
        }
        __syncthreads();   // avs/tas reads done -> pool reusable
        #pragma unroll
        for (int r=0;r<4;r++){
            const int rr = rg*4 + r;
            if (rr < nrem) {
                const float4 xv = *(const float4*)&x[(n0+rr)*64 + cg*4];
                *(float4*)&osh[rr*68 + cg*4] =
                    make_float4(acc[r][0]+xv.x, acc[r][1]+xv.y, acc[r][2]+xv.z, acc[r][3]+xv.w);
            }
        }
        __syncthreads();
        // ---- stage C: LN2 (4 threads/node) -> hsh ----
        {
            float v0[16];
            #pragma unroll
            for (int q=0;q<4;q++){
                float4 a = *(const float4*)&osh[nodeq*68 + partq*16 + q*4];
                v0[q*4+0]=a.x; v0[q*4+1]=a.y; v0[q*4+2]=a.z; v0[q*4+3]=a.w;
            }
            float s=0.f, ss=0.f;
            #pragma unroll
            for (int i=0;i<16;i++){ s+=v0[i]; ss+=v0[i]*v0[i]; }
            s  += __shfl_xor_sync(0xffffffffu, s, 1);  ss += __shfl_xor_sync(0xffffffffu, ss, 1);
            s  += __shfl_xor_sync(0xffffffffu, s, 2);  ss += __shfl_xor_sync(0xffffffffu, ss, 2);
            const float mean = s*(1.f/64.f);
            const float rstd = rsqrtf(ss*(1.f/64.f) - mean*mean + 1e-5f);
            const int c = partq*16;
            #pragma unroll
            for (int i=0;i<16;i++)
                hsh[nodeq*68 + c + i] = (v0[i]-mean)*rstd*lgs[c+i] + lbs[c+i];
        }
        __syncthreads();
        // ---- stage D: mid = gelu(h @ W1 + b1) -> msh ----
        {
            float ac[4][4];
            const float4 b1v = *(const float4*)&b1s[cg*4];
            #pragma unroll
            for (int r=0;r<4;r++){ ac[r][0]=b1v.x; ac[r][1]=b1v.y; ac[r][2]=b1v.z; ac[r][3]=b1v.w; }
            #pragma unroll 2
            for (int kk = 0; kk < 64; kk += 4) {
                float4 h4[4], w[4];
                #pragma unroll
                for (int r=0;r<4;r++) h4[r] = *(const float4*)&hsh[(rg*4+r)*68 + kk];
                #pragma unroll
                for (int i=0;i<4;i++) w[i] = *(const float4*)&W1s[(kk+i)*64 + cg*4];
                #pragma unroll
                for (int r=0;r<4;r++){
                    ac[r][0]+=h4[r].x*w[0].x + h4[r].y*w[1].x + h4[r].z*w[2].x + h4[r].w*w[3].x;
                    ac[r][1]+=h4[r].x*w[0].y + h4[r].y*w[1].y + h4[r].z*w[2].y + h4[r].w*w[3].y;
                    ac[r][2]+=h4[r].x*w[0].z + h4[r].y*w[1].z + h4[r].z*w[2].z + h4[r].w*w[3].z;
                    ac[r][3]+=h4[r].x*w[0].w + h4[r].y*w[1].w + h4[r].z*w[2].w + h4[r].w*w[3].w;
                }
            }
            #pragma unroll
            for (int r=0;r<4;r++){
                float4 mo;
                mo.x = 0.5f*ac[r][0]*(1.f + erff(ac[r][0]*0.70710678118654752f));
                mo.y = 0.5f*ac[r][1]*(1.f + erff(ac[r][1]*0.70710678118654752f));
                mo.z = 0.5f*ac[r][2]*(1.f + erff(ac[r][2]*0.70710678118654752f));
                mo.w = 0.5f*ac[r][3]*(1.f + erff(ac[r][3]*0.70710678118654752f));
                *(float4*)&msh[(rg*4+r)*68 + cg*4] = mo;
            }
        }
        __syncthreads();
        // ---- stage E: out = mid @ W2 + b2 + out1 ----
        {
            float ac[4][4];
            const float4 b2v = *(const float4*)&b2s[cg*4];
            #pragma unroll
            for (int r=0;r<4;r++){ ac[r][0]=b2v.x; ac[r][1]=b2v.y; ac[r][2]=b2v.z; ac[r][3]=b2v.w; }
            #pragma unroll 2
            for (int kk = 0; kk < 64; kk += 4) {
                float4 m[4], w[4];
                #pragma unroll
                for (int r=0;r<4;r++) m[r] = *(const float4*)&msh[(rg*4+r)*68 + kk];
                #pragma unroll
                for (int i=0;i<4;i++) w[i] = __ldg(&w24[(kk+i)*16 + cg]);
                #pragma unroll
                for (int r=0;r<4;r++){
                    ac[r][0]+=m[r].x*w[0].x + m[r].y*w[1].x + m[r].z*w[2].x + m[r].w*w[3].x;
                    ac[r][1]+=m[r].x*w[0].y + m[r].y*w[1].y + m[r].z*w[2].y + m[r].w*w[3].y;
                    ac[r][2]+=m[r].x*w[0].z + m[r].y*w[1].z + m[r].z*w[2].z + m[r].w*w[3].z;
                    ac[r][3]+=m[r].x*w[0].w + m[r].y*w[1].w + m[r].z*w[2].w + m[r].w*w[3].w;
                }
            }
            #pragma unroll
            for (int r=0;r<4;r++){
                const int rr = rg*4 + r;
                if (rr < nrem) {
                    const float4 ov = *(const float4*)&osh[rr*68 + cg*4];
                    *(float4*)&out[(n0+rr)*64 + cg*4] =
                        make_float4(ac[r][0]+ov.x, ac[r][1]+ov.y, ac[r][2]+ov.z, ac[r][3]+ov.w);
                }
            }
        }
        __syncthreads();
    }
}

// ---------------- host launcher ----------------
extern "C" void kernel_launch(void* const* d_in, const int* in_sizes, int n_in,
                              void* d_out, int out_size)
{
    const float* x   = (const float*)d_in[0];
    const int*   ei  = (const int*)d_in[1];
    const float* ea  = (const float*)d_in[2];
    const float* Wq  = (const float*)d_in[3];
    const float* bq  = (const float*)d_in[4];
    const float* Wk  = (const float*)d_in[5];
    const float* bk  = (const float*)d_in[6];
    const float* Wv  = (const float*)d_in[7];
    const float* bv  = (const float*)d_in[8];
    const float* We  = (const float*)d_in[9];
    const float* Wp  = (const float*)d_in[10];
    const float* bp  = (const float*)d_in[11];
    const float* l1g = (const float*)d_in[12];
    const float* l1b = (const float*)d_in[13];
    const float* l2g = (const float*)d_in[14];
    const float* l2b = (const float*)d_in[15];
    const float* W1  = (const float*)d_in[16];
    const float* b1  = (const float*)d_in[17];
    const float* W2  = (const float*)d_in[18];
    const float* b2  = (const float*)d_in[19];

    const int n = in_sizes[0] / 64;
    const int e = in_sizes[2] / 32;

    const int SMEM_K1  = (64*384 + 384 + 64*68 + 64*132 + 128*36) * (int)sizeof(float); // ~166 KB
    const int SMEM_AE  = (8192 + 4096 + 5*64 + 13056) * (int)sizeof(float);             // ~100 KB
    cudaFuncSetAttribute(k_ln_qkv, cudaFuncAttributeMaxDynamicSharedMemorySize, SMEM_K1);
    cudaFuncSetAttribute(k_aggepi, cudaFuncAttributeMaxDynamicSharedMemorySize, SMEM_AE);

    const int fb = (e + 1023) / 1024;

    k_ln_qkv<<<148, 512, SMEM_K1>>>(x, ei, Wq, bq, Wk, bk, Wv, bv, We, l1g, l1b, n, e);
    k_scanfill<<<fb, 1024>>>(ei, We, Wp, e, n);
    k_aggepi<<<296, 256, SMEM_AE>>>((float*)d_out, x, ea, Wp, bp,
                                    l2g, l2b, W1, b1, W2, b2, n);
}

// round 17
// speedup vs baseline: 1.2835x; 1.2835x over previous
#include <cuda_runtime.h>
#include <math.h>

#define NN 50000
#define EE 600000

// ---------------- scratch (device globals; allocation-free) ----------------
__device__ float g_q[NN*128];
__device__ float g_k[NN*128];
__device__ float g_v[NN*128];
__device__ float g_qt[NN*64];
__device__ float g_aggv[NN*128];
__device__ float g_tacc[NN*64];
__device__ float g_Wc[64*64];       // per-head We@Wp fold
__device__ int   g_deg[NN];
__device__ int   g_rowstart[NN+1];
__device__ int   g_cursor[NN];
__device__ int2  g_csr[EE];
__device__ int   g_psum[32];        // per-chunk totals
__device__ int   g_base[32];        // per-chunk bases
__device__ int   g_cnt;             // chunks that published totals
__device__ int   g_base_ready;      // bases published flag
__device__ int   g_store_done;      // chunks that stored rowstart/cursor

// ---------------- K1: edge-count + LN1 + QKV GEMM + qt GEMM (64-node tiles) -
__global__ void __launch_bounds__(512) k_ln_qkv(
    const float* __restrict__ x,  const int* __restrict__ ei,
    const float* __restrict__ Wq, const float* __restrict__ bq,
    const float* __restrict__ Wk, const float* __restrict__ bk,
    const float* __restrict__ Wv, const float* __restrict__ bv,
    const float* __restrict__ We,
    const float* __restrict__ g1, const float* __restrict__ b1, int n, int e)
{
    extern __shared__ float sm[];
    float* Ws = sm;               // 64*384
    float* bs = Ws + 64*384;      // 384
    float* hs = bs + 384;         // 64*68
    float* qs = hs + 64*68;       // 64*132
    float* Wt = qs + 64*132;      // 128*36
    const int tid = threadIdx.x;

    for (int ed = blockIdx.x*blockDim.x + tid; ed < e; ed += gridDim.x*blockDim.x)
        atomicAdd(&g_deg[ei[e + ed]], 1);

    for (int i = tid; i < 64*128; i += 512) {
        int kk = i >> 7, c = i & 127;
        Ws[kk*384 + c]       = Wq[i];
        Ws[kk*384 + 128 + c] = Wk[i];
        Ws[kk*384 + 256 + c] = Wv[i];
    }
    if (tid < 384) bs[tid] = (tid < 128) ? bq[tid] : (tid < 256 ? bk[tid-128] : bv[tid-256]);
    for (int i = tid; i < 32*128; i += 512) {
        int d = i & 31, cg = i >> 5;
        Wt[cg*36 + d] = We[d*128 + cg];
    }
    __syncthreads();
    const int tx = tid & 31, ty = tid >> 5;
    const int node64 = tid >> 3, part = tid & 7;
    const int tx16 = tid & 15, ty16 = tid >> 4;
    const int hql = tx16 >> 3;
    const int dq  = (tx16 & 7) * 4;
    const int ntiles = (n + 63) >> 6;
    for (int tile = blockIdx.x; tile < ntiles; tile += gridDim.x) {
        const int n0 = tile << 6;
        {   // LayerNorm
            int gn = n0 + node64;
            float v0[8];
            if (gn < n) {
                float4 a  = *(const float4*)&x[gn*64 + part*8];
                float4 b4 = *(const float4*)&x[gn*64 + part*8 + 4];
                v0[0]=a.x; v0[1]=a.y; v0[2]=a.z; v0[3]=a.w;
                v0[4]=b4.x; v0[5]=b4.y; v0[6]=b4.z; v0[7]=b4.w;
            } else {
                #pragma unroll
                for (int i=0;i<8;i++) v0[i]=0.f;
            }
            float s=0.f, ss=0.f;
            #pragma unroll
            for (int i=0;i<8;i++){ s+=v0[i]; ss+=v0[i]*v0[i]; }
            #pragma unroll
            for (int m=1;m<8;m<<=1){
                s  += __shfl_xor_sync(0xffffffffu, s,  m);
                ss += __shfl_xor_sync(0xffffffffu, ss, m);
            }
            float mean = s*(1.f/64.f);
            float rstd = rsqrtf(ss*(1.f/64.f) - mean*mean + 1e-5f);
            int c = part*8;
            #pragma unroll
            for (int i=0;i<8;i++)
                hs[node64*68 + c + i] = (v0[i]-mean)*rstd*g1[c+i] + b1[c+i];
        }
        __syncthreads();
        {   // QKV GEMM
            float aq[4][4], ak[4][4], av[4][4];
            const float4 bqv = *(const float4*)&bs[tx*4];
            const float4 bkv = *(const float4*)&bs[128 + tx*4];
            const float4 bvv = *(const float4*)&bs[256 + tx*4];
            #pragma unroll
            for (int i=0;i<4;i++){
                aq[i][0]=bqv.x; aq[i][1]=bqv.y; aq[i][2]=bqv.z; aq[i][3]=bqv.w;
                ak[i][0]=bkv.x; ak[i][1]=bkv.y; ak[i][2]=bkv.z; ak[i][3]=bkv.w;
                av[i][0]=bvv.x; av[i][1]=bvv.y; av[i][2]=bvv.z; av[i][3]=bvv.w;
            }
            #pragma unroll 4
            for (int kk=0; kk<64; kk++) {
                const float4 wq = *(const float4*)&Ws[kk*384 + tx*4];
                const float4 wk = *(const float4*)&Ws[kk*384 + 128 + tx*4];
                const float4 wv = *(const float4*)&Ws[kk*384 + 256 + tx*4];
                #pragma unroll
                for (int i=0;i<4;i++){
                    const float h = hs[(ty*4+i)*68 + kk];
                    aq[i][0]+=h*wq.x; aq[i][1]+=h*wq.y; aq[i][2]+=h*wq.z; aq[i][3]+=h*wq.w;
                    ak[i][0]+=h*wk.x; ak[i][1]+=h*wk.y; ak[i][2]+=h*wk.z; ak[i][3]+=h*wk.w;
                    av[i][0]+=h*wv.x; av[i][1]+=h*wv.y; av[i][2]+=h*wv.z; av[i][3]+=h*wv.w;
                }
            }
            #pragma unroll
            for (int i=0;i<4;i++){
                const int r = ty*4 + i;
                const int gn = n0 + r;
                const float4 qv = make_float4(aq[i][0],aq[i][1],aq[i][2],aq[i][3]);
                *(float4*)&qs[r*132 + tx*4] = qv;
                if (gn < n) {
                    *(float4*)&g_q[gn*128 + tx*4] = qv;
                    *(float4*)&g_k[gn*128 + tx*4] = make_float4(ak[i][0],ak[i][1],ak[i][2],ak[i][3]);
                    *(float4*)&g_v[gn*128 + tx*4] = make_float4(av[i][0],av[i][1],av[i][2],av[i][3]);
                }
            }
        }
        __syncthreads();
        {   // qt GEMM
            float a2[2][4] = {{0.f,0.f,0.f,0.f},{0.f,0.f,0.f,0.f}};
            const int cbase = hql*64;
            #pragma unroll 4
            for (int c=0; c<64; c++) {
                const float4 w = *(const float4*)&Wt[(cbase + c)*36 + dq];
                const float q0 = qs[(ty16*2+0)*132 + cbase + c];
                const float q1 = qs[(ty16*2+1)*132 + cbase + c];
                a2[0][0]+=q0*w.x; a2[0][1]+=q0*w.y; a2[0][2]+=q0*w.z; a2[0][3]+=q0*w.w;
                a2[1][0]+=q1*w.x; a2[1][1]+=q1*w.y; a2[1][2]+=q1*w.z; a2[1][3]+=q1*w.w;
            }
            #pragma unroll
            for (int r=0;r<2;r++){
                const int gn = n0 + ty16*2 + r;
                if (gn < n)
                    *(float4*)&g_qt[gn*64 + tx16*4] =
                        make_float4(a2[r][0],a2[r][1],a2[r][2],a2[r][3]);
            }
        }
        __syncthreads();
    }
}

// -- K2: PARALLEL chunk scan + Wc fold (block nchunk) + CSR fill -------------
__global__ void __launch_bounds__(1024) k_scanfill(
    const int* __restrict__ ei, const float* __restrict__ We,
    const float* __restrict__ Wp, int e, int n)
{
    const int tid = threadIdx.x;
    const int nchunk = (n + 4095) >> 12;
    if ((int)blockIdx.x < nchunk) {
        __shared__ int buf[4096];
        __shared__ int wsum[32];
        const int b = blockIdx.x;
        const int base_i = b << 12;
        const int lane = tid & 31, w = tid >> 5;
        #pragma unroll
        for (int k = 0; k < 4; k++) {
            int idx = base_i + tid + k*1024;
            buf[tid + k*1024] = (idx < n) ? g_deg[idx] : 0;
        }
        __syncthreads();
        const int v0 = buf[tid*4], v1 = buf[tid*4+1], v2 = buf[tid*4+2], v3 = buf[tid*4+3];
        const int tsum = v0+v1+v2+v3;
        int sc = tsum;
        #pragma unroll
        for (int o=1;o<32;o<<=1){ int t2=__shfl_up_sync(0xffffffffu, sc, o); if(lane>=o) sc+=t2; }
        if (lane==31) wsum[w]=sc;
        __syncthreads();
        if (w==0){
            int s2 = wsum[lane];
            #pragma unroll
            for (int o=1;o<32;o<<=1){ int t2=__shfl_up_sync(0xffffffffu, s2, o); if(lane>=o) s2+=t2; }
            wsum[lane]=s2;
        }
        __syncthreads();
        if (tid == 0) {
            g_psum[b] = wsum[31];
            __threadfence();
            atomicAdd(&g_cnt, 1);
        }
        // block 0 scans the chunk totals and publishes bases
        if (b == 0 && tid == 0) {
            while (atomicAdd(&g_cnt, 0) < nchunk) __nanosleep(64);
            int run = 0;
            for (int i = 0; i < nchunk; i++) { g_base[i] = run; run += g_psum[i]; }
            g_rowstart[n] = run;
            __threadfence();
            atomicExch(&g_base_ready, 1);
        }
        if (tid == 0) { while (atomicAdd(&g_base_ready, 0) == 0) __nanosleep(64); }
        __syncthreads();
        const int excl = sc - tsum + (w>0 ? wsum[w-1] : 0) + g_base[b];
        const int p0 = excl, p1 = p0+v0, p2 = p1+v1, p3 = p2+v2;
        const int gidx = base_i + tid*4;
        if (gidx + 3 < n) {
            g_rowstart[gidx]=p0; g_rowstart[gidx+1]=p1; g_rowstart[gidx+2]=p2; g_rowstart[gidx+3]=p3;
            g_cursor[gidx]=p0;   g_cursor[gidx+1]=p1;   g_cursor[gidx+2]=p2;   g_cursor[gidx+3]=p3;
        } else {
            const int pv[4] = {p0,p1,p2,p3};
            #pragma unroll
            for (int k2=0;k2<4;k2++)
                if (gidx+k2 < n) { g_rowstart[gidx+k2]=pv[k2]; g_cursor[gidx+k2]=pv[k2]; }
        }
        __syncthreads();
        if (tid == 0) { __threadfence(); atomicAdd(&g_store_done, 1); }
    } else if ((int)blockIdx.x == nchunk) {
        // Wc fold (independent of scan)
        for (int i = tid; i < 4096; i += 1024) {
            const int kk = i >> 6;
            const int c  = i & 63;
            const int h  = kk >> 5, d = kk & 31;
            const float* wer = We + d*128 + h*64;
            const float* wpr = Wp + (h*64)*64 + c;
            float s = 0.f;
            #pragma unroll 8
            for (int t = 0; t < 64; t++) s += wer[t] * wpr[t*64];
            g_Wc[kk*64 + c] = s;
        }
    }
    // all blocks wait for cursors, then fill
    if (tid == 0) { while (atomicAdd(&g_store_done, 0) < nchunk) __nanosleep(128); }
    __syncthreads();
    const int gtid = blockIdx.x*blockDim.x + tid;
    const int stride = gridDim.x*blockDim.x;
    for (int ed = gtid; ed < e; ed += stride) {
        const int src = ei[ed];
        const int tgt = ei[e + ed];
        const int pos = atomicAdd(&g_cursor[tgt], 1);
        g_csr[pos] = make_int2(src, ed);
    }
    for (int i = gtid; i < n; i += stride) g_deg[i] = 0;
}

// ---------------- K3: single-pass aggregation (ILP-2, regs~40) --------------
__global__ void __launch_bounds__(256) k_agg(const float* __restrict__ ea, int n)
{
    const int warp = threadIdx.x >> 5, lane = threadIdx.x & 31;
    const int h = lane >> 4, j = lane & 15;
    for (int node = blockIdx.x*8 + warp; node < n; node += gridDim.x*8) {
        const int r0 = g_rowstart[node], r1 = g_rowstart[node + 1];
        const float4 q4  = *(const float4*)&g_q[node*128 + lane*4];
        const float2 qt2 = *(const float2*)&g_qt[node*64 + h*32 + j*2];
        float den = 0.f;
        float4 acc = make_float4(0.f, 0.f, 0.f, 0.f);
        float2 tac = make_float2(0.f, 0.f);
        int p = r0;
        for (; p + 1 < r1; p += 2) {
            const int2 se0 = g_csr[p];
            const int2 se1 = g_csr[p+1];
            const float4 k0 = *(const float4*)&g_k[se0.x*128 + lane*4];
            const float4 k1 = *(const float4*)&g_k[se1.x*128 + lane*4];
            const float4 v0 = *(const float4*)&g_v[se0.x*128 + lane*4];
            const float4 v1 = *(const float4*)&g_v[se1.x*128 + lane*4];
            const float2 e0 = *(const float2*)&ea[se0.y*32 + j*2];
            const float2 e1 = *(const float2*)&ea[se1.y*32 + j*2];
            float s0 = q4.x*k0.x + q4.y*k0.y + q4.z*k0.z + q4.w*k0.w
                     + qt2.x*e0.x + qt2.y*e0.y;
            float s1 = q4.x*k1.x + q4.y*k1.y + q4.z*k1.z + q4.w*k1.w
                     + qt2.x*e1.x + qt2.y*e1.y;
            #pragma unroll
            for (int mm = 1; mm < 16; mm <<= 1) {
                s0 += __shfl_xor_sync(0xffffffffu, s0, mm);
                s1 += __shfl_xor_sync(0xffffffffu, s1, mm);
            }
            const float ex0 = __expf(s0 * 0.125f);
            const float ex1 = __expf(s1 * 0.125f);
            den += ex0 + ex1;
            acc.x += ex0*v0.x + ex1*v1.x;
            acc.y += ex0*v0.y + ex1*v1.y;
            acc.z += ex0*v0.z + ex1*v1.z;
            acc.w += ex0*v0.w + ex1*v1.w;
            tac.x += ex0*e0.x + ex1*e1.x;
            tac.y += ex0*e0.y + ex1*e1.y;
        }
        if (p < r1) {
            const int2 se = g_csr[p];
            const float4 k4 = *(const float4*)&g_k[se.x*128 + lane*4];
            const float4 v4 = *(const float4*)&g_v[se.x*128 + lane*4];
            const float2 e2 = *(const float2*)&ea[se.y*32 + j*2];
            float s = q4.x*k4.x + q4.y*k4.y + q4.z*k4.z + q4.w*k4.w
                    + qt2.x*e2.x + qt2.y*e2.y;
            #pragma unroll
            for (int mm = 1; mm < 16; mm <<= 1) s += __shfl_xor_sync(0xffffffffu, s, mm);
            const float ex = __expf(s * 0.125f);
            den += ex;
            acc.x += ex*v4.x; acc.y += ex*v4.y; acc.z += ex*v4.z; acc.w += ex*v4.w;
            tac.x += ex*e2.x; tac.y += ex*e2.y;
        }
        const float inv = 1.f / (den + 1e-8f);
        acc.x *= inv; acc.y *= inv; acc.z *= inv; acc.w *= inv;
        tac.x *= inv; tac.y *= inv;
        *(float4*)&g_aggv[node*128 + lane*4]    = acc;
        *(float2*)&g_tacc[node*64 + h*32 + j*2] = tac;
    }
}

// ------ K4: fused epilogue, scalar 4x4 tiles, 64-node tiles, 2 CTA/SM -------
__global__ void __launch_bounds__(256) k_epi(
    float* __restrict__ out,
    const float* __restrict__ x,
    const float* __restrict__ Wp,  const float* __restrict__ bp,
    const float* __restrict__ lg,  const float* __restrict__ lb,
    const float* __restrict__ W1,  const float* __restrict__ b1,
    const float* __restrict__ W2,  const float* __restrict__ b2, int n)
{
    extern __shared__ float sm[];
    float* Wps = sm;               // 8192
    float* W1s = Wps + 8192;       // 4096
    float* bps = W1s + 4096;       // 64
    float* b1s = bps + 64;
    float* b2s = b1s + 64;
    float* lgs = b2s + 64;
    float* lbs = lgs + 64;
    float* pool = lbs + 64;        // 13056 floats, aliased across stages
    float* avs = pool;             // [64][128] during load+B
    float* tas = pool + 8192;      // [64][64]
    float* osh = pool;             // [64][68] after B
    float* hsh = pool + 4352;      // [64][68]
    float* msh = pool + 8704;      // [64][68]
    const int tid = threadIdx.x;
    if (blockIdx.x == 0 && tid == 0) {   // reset sync counters for next replay
        atomicExch(&g_cnt, 0);
        atomicExch(&g_base_ready, 0);
        atomicExch(&g_store_done, 0);
    }
    for (int i = tid; i < 8192; i += 256) Wps[i] = Wp[i];
    for (int i = tid; i < 4096; i += 256) W1s[i] = W1[i];
    if (tid < 64) { bps[tid]=bp[tid]; b1s[tid]=b1[tid]; b2s[tid]=b2[tid];
                    lgs[tid]=lg[tid]; lbs[tid]=lb[tid]; }
    __syncthreads();
    const int cg = tid & 15;
    const int rg = tid >> 4;
    const int nodeq = tid >> 2, partq = tid & 3;
    const float4* wc4 = (const float4*)g_Wc;
    const float4* w24 = (const float4*)W2;
    const int ntiles = (n + 63) >> 6;
    for (int tile = blockIdx.x; tile < ntiles; tile += gridDim.x) {
        const int n0 = tile << 6;
        const int nrem = n - n0;
        {
            const float4* ga = (const float4*)(g_aggv + n0*128);
            const float4* gt = (const float4*)(g_tacc + n0*64);
            const int lim_a = (nrem >= 64 ? 2048 : nrem*32);
            const int lim_t = (nrem >= 64 ? 1024 : nrem*16);
            for (int i2 = tid; i2 < lim_a; i2 += 256) ((float4*)avs)[i2] = ga[i2];
            for (int i2 = tid; i2 < lim_t; i2 += 256) ((float4*)tas)[i2] = gt[i2];
        }
        __syncthreads();
        // ---- stage B: acc = aggv@Wp + tacc@Wc + bp ----
        float acc[4][4];
        {
            const float4 bpv = *(const float4*)&bps[cg*4];
            #pragma unroll
            for (int r=0;r<4;r++){ acc[r][0]=bpv.x; acc[r][1]=bpv.y; acc[r][2]=bpv.z; acc[r][3]=bpv.w; }
            #pragma unroll 2
            for (int kk = 0; kk < 128; kk += 4) {
                float4 a[4], w[4];
                #pragma unroll
                for (int r=0;r<4;r++) a[r] = *(const float4*)&avs[(rg*4+r)*128 + kk];
                #pragma unroll
                for (int i=0;i<4;i++) w[i] = *(const float4*)&Wps[(kk+i)*64 + cg*4];
                #pragma unroll
                for (int r=0;r<4;r++){
                    acc[r][0]+=a[r].x*w[0].x + a[r].y*w[1].x + a[r].z*w[2].x + a[r].w*w[3].x;
                    acc[r][1]+=a[r].x*w[0].y + a[r].y*w[1].y + a[r].z*w[2].y + a[r].w*w[3].y;
                    acc[r][2]+=a[r].x*w[0].z + a[r].y*w[1].z + a[r].z*w[2].z + a[r].w*w[3].z;
                    acc[r][3]+=a[r].x*w[0].w + a[r].y*w[1].w + a[r].z*w[2].w + a[r].w*w[3].w;
                }
            }
            #pragma unroll 2
            for (int kk = 0; kk < 64; kk += 4) {
                float4 t[4], w[4];
                #pragma unroll
                for (int r=0;r<4;r++) t[r] = *(const float4*)&tas[(rg*4+r)*64 + kk];
                #pragma unroll
                for (int i=0;i<4;i++) w[i] = __ldg(&wc4[(kk+i)*16 + cg]);
                #pragma unroll
                for (int r=0;r<4;r++){
                    acc[r][0]+=t[r].x*w[0].x + t[r].y*w[1].x + t[r].z*w[2].x + t[r].w*w[3].x;
                    acc[r][1]+=t[r].x*w[0].y + t[r].y*w[1].y + t[r].z*w[2].y + t[r].w*w[3].y;
                    acc[r][2]+=t[r].x*w[0].z + t[r].y*w[1].z + t[r].z*w[2].z + t[r].w*w[3].z;
                    acc[r][3]+=t[r].x*w[0].w + t[r].y*w[1].w + t[r].z*w[2].w + t[r].w*w[3].w;
                }
            }
        }
        __syncthreads();
        #pragma unroll
        for (int r=0;r<4;r++){
            const int rr = rg*4 + r;
            if (rr < nrem) {
                const float4 xv = *(const float4*)&x[(n0+rr)*64 + cg*4];
                *(float4*)&osh[rr*68 + cg*4] =
                    make_float4(acc[r][0]+xv.x, acc[r][1]+xv.y, acc[r][2]+xv.z, acc[r][3]+xv.w);
            }
        }
        __syncthreads();
        // ---- stage C: LN2 (4 threads/node) -> hsh ----
        {
            float v0[16];
            #pragma unroll
            for (int q=0;q<4;q++){
                float4 a = *(const float4*)&osh[nodeq*68 + partq*16 + q*4];
                v0[q*4+0]=a.x; v0[q*4+1]=a.y; v0[q*4+2]=a.z; v0[q*4+3]=a.w;
            }
            float s=0.f, ss=0.f;
            #pragma unroll
            for (int i=0;i<16;i++){ s+=v0[i]; ss+=v0[i]*v0[i]; }
            s  += __shfl_xor_sync(0xffffffffu, s, 1);  ss += __shfl_xor_sync(0xffffffffu, ss, 1);
            s  += __shfl_xor_sync(0xffffffffu, s, 2);  ss += __shfl_xor_sync(0xffffffffu, ss, 2);
            const float mean = s*(1.f/64.f);
            const float rstd = rsqrtf(ss*(1.f/64.f) - mean*mean + 1e-5f);
            const int c = partq*16;
            #pragma unroll
            for (int i=0;i<16;i++)
                hsh[nodeq*68 + c + i] = (v0[i]-mean)*rstd*lgs[c+i] + lbs[c+i];
        }
        __syncthreads();
        // ---- stage D: mid = gelu(h @ W1 + b1) -> msh ----
        {
            float ac[4][4];
            const float4 b1v = *(const float4*)&b1s[cg*4];
            #pragma unroll
            for (int r=0;r<4;r++){ ac[r][0]=b1v.x; ac[r][1]=b1v.y; ac[r][2]=b1v.z; ac[r][3]=b1v.w; }
            #pragma unroll 2
            for (int kk = 0; kk < 64; kk += 4) {
                float4 h[4], w[4];
                #pragma unroll
                for (int r=0;r<4;r++) h[r] = *(const float4*)&hsh[(rg*4+r)*68 + kk];
                #pragma unroll
                for (int i=0;i<4;i++) w[i] = *(const float4*)&W1s[(kk+i)*64 + cg*4];
                #pragma unroll
                for (int r=0;r<4;r++){
                    ac[r][0]+=h[r].x*w[0].x + h[r].y*w[1].x + h[r].z*w[2].x + h[r].w*w[3].x;
                    ac[r][1]+=h[r].x*w[0].y + h[r].y*w[1].y + h[r].z*w[2].y + h[r].w*w[3].y;
                    ac[r][2]+=h[r].x*w[0].z + h[r].y*w[1].z + h[r].z*w[2].z + h[r].w*w[3].z;
                    ac[r][3]+=h[r].x*w[0].w + h[r].y*w[1].w + h[r].z*w[2].w + h[r].w*w[3].w;
                }
            }
            #pragma unroll
            for (int r=0;r<4;r++){
                float4 mo;
                mo.x = 0.5f*ac[r][0]*(1.f + erff(ac[r][0]*0.70710678118654752f));
                mo.y = 0.5f*ac[r][1]*(1.f + erff(ac[r][1]*0.70710678118654752f));
                mo.z = 0.5f*ac[r][2]*(1.f + erff(ac[r][2]*0.70710678118654752f));
                mo.w = 0.5f*ac[r][3]*(1.f + erff(ac[r][3]*0.70710678118654752f));
                *(float4*)&msh[(rg*4+r)*68 + cg*4] = mo;
            }
        }
        __syncthreads();
        // ---- stage E: out = mid @ W2 + b2 + out1 ----
        {
            float ac[4][4];
            const float4 b2v = *(const float4*)&b2s[cg*4];
            #pragma unroll
            for (int r=0;r<4;r++){ ac[r][0]=b2v.x; ac[r][1]=b2v.y; ac[r][2]=b2v.z; ac[r][3]=b2v.w; }
            #pragma unroll 2
            for (int kk = 0; kk < 64; kk += 4) {
                float4 m[4], w[4];
                #pragma unroll
                for (int r=0;r<4;r++) m[r] = *(const float4*)&msh[(rg*4+r)*68 + kk];
                #pragma unroll
                for (int i=0;i<4;i++) w[i] = __ldg(&w24[(kk+i)*16 + cg]);
                #pragma unroll
                for (int r=0;r<4;r++){
                    ac[r][0]+=m[r].x*w[0].x + m[r].y*w[1].x + m[r].z*w[2].x + m[r].w*w[3].x;
                    ac[r][1]+=m[r].x*w[0].y + m[r].y*w[1].y + m[r].z*w[2].y + m[r].w*w[3].y;
                    ac[r][2]+=m[r].x*w[0].z + m[r].y*w[1].z + m[r].z*w[2].z + m[r].w*w[3].z;
                    ac[r][3]+=m[r].x*w[0].w + m[r].y*w[1].w + m[r].z*w[2].w + m[r].w*w[3].w;
                }
            }
            #pragma unroll
            for (int r=0;r<4;r++){
                const int rr = rg*4 + r;
                if (rr < nrem) {
                    const float4 ov = *(const float4*)&osh[rr*68 + cg*4];
                    *(float4*)&out[(n0+rr)*64 + cg*4] =
                        make_float4(ac[r][0]+ov.x, ac[r][1]+ov.y, ac[r][2]+ov.z, ac[r][3]+ov.w);
                }
            }
        }
        __syncthreads();
    }
}

// ---------------- host launcher ----------------
extern "C" void kernel_launch(void* const* d_in, const int* in_sizes, int n_in,
                              void* d_out, int out_size)
{
    const float* x   = (const float*)d_in[0];
    const int*   ei  = (const int*)d_in[1];
    const float* ea  = (const float*)d_in[2];
    const float* Wq  = (const float*)d_in[3];
    const float* bq  = (const float*)d_in[4];
    const float* Wk  = (const float*)d_in[5];
    const float* bk  = (const float*)d_in[6];
    const float* Wv  = (const float*)d_in[7];
    const float* bv  = (const float*)d_in[8];
    const float* We  = (const float*)d_in[9];
    const float* Wp  = (const float*)d_in[10];
    const float* bp  = (const float*)d_in[11];
    const float* l1g = (const float*)d_in[12];
    const float* l1b = (const float*)d_in[13];
    const float* l2g = (const float*)d_in[14];
    const float* l2b = (const float*)d_in[15];
    const float* W1  = (const float*)d_in[16];
    const float* b1  = (const float*)d_in[17];
    const float* W2  = (const float*)d_in[18];
    const float* b2  = (const float*)d_in[19];

    const int n = in_sizes[0] / 64;
    const int e = in_sizes[2] / 32;

    const int SMEM_K1  = (64*384 + 384 + 64*68 + 64*132 + 128*36) * (int)sizeof(float); // ~166 KB
    const int SMEM_EPI = (8192 + 4096 + 5*64 + 13056) * (int)sizeof(float);             // ~100 KB
    cudaFuncSetAttribute(k_ln_qkv, cudaFuncAttributeMaxDynamicSharedMemorySize, SMEM_K1);
    cudaFuncSetAttribute(k_epi,    cudaFuncAttributeMaxDynamicSharedMemorySize, SMEM_EPI);

    const int nb8 = (n + 7) / 8;
    const int fb  = (e + 1023) / 1024;

    k_ln_qkv<<<148, 512, SMEM_K1>>>(x, ei, Wq, bq, Wk, bk, Wv, bv, We, l1g, l1b, n, e);
    k_scanfill<<<fb, 1024>>>(ei, We, Wp, e, n);
    k_agg<<<nb8, 256>>>(ea, n);
    k_epi<<<296, 256, SMEM_EPI>>>((float*)d_out, x, Wp, bp,
                                  l2g, l2b, W1, b1, W2, b2, n);
}